// round 1
// baseline (speedup 1.0000x reference)
#include <cuda_runtime.h>
#include <cuda_fp16.h>
#include <cstdint>

// ----------------------------------------------------------------------------
// CrossAttention_30056181138117 on GB300 (sm_103a)
//
// Key simplification: seq-len-1 attention => softmax over a single element is
// exactly 1.0 => attn output == V projection. So:
//   dna_att = mol @ Wc1^T + c1,  Wc1 = a1_out_w @ wv1,  c1 = a1_out_w @ bv1 + a1_out_b
//   mol_att = dna @ Wc2^T + c2
// Then per stream: h = LN(res + att); u = relu(h@w1^T+b1); o = LN(h + u@w2^T+b2)
// Output = concat(o_dna, o_mol).
//
// GEMMs use mma.sync.m16n8k16 f16 (fp32 accumulate). BM=128,BN=64,BK=32,
// 8 warps, warp tile 32x32.
// ----------------------------------------------------------------------------

#define MROWS 32768
#define EDIM  512
#define FFDIM 1024

#define BM 128
#define BN 64
#define BK 32
#define SPAD 8
#define LDS (BK + SPAD)   // 40 halfs per smem row -> conflict-free frag loads

// ------------------------- device scratch (static, no allocs) ---------------
__device__ __half g_xh0[MROWS * EDIM];      // dna fp16
__device__ __half g_xh1[MROWS * EDIM];      // mol fp16
__device__ __half g_h  [MROWS * EDIM];      // LN1 output fp16 (GEMM input + residual)
__device__ __half g_u  [MROWS * FFDIM];     // FFN hidden fp16
__device__ float  g_t  [MROWS * EDIM];      // pre-LN fp32 buffer
__device__ __half g_wc [2 * EDIM * EDIM];   // folded attn weights fp16
__device__ float  g_c  [2 * EDIM];          // folded attn bias fp32
__device__ __half g_w1h[2 * FFDIM * EDIM];  // ffn w1 fp16
__device__ __half g_w2h[2 * EDIM * FFDIM];  // ffn w2 fp16

// ------------------------- fp32 -> fp16 convert ------------------------------
__global__ void k_f2h(const float* __restrict__ src, __half* __restrict__ dst, int n) {
    int i = (blockIdx.x * blockDim.x + threadIdx.x) * 4;
    if (i >= n) return;
    float4 v = *(const float4*)(src + i);
    __half2 h0 = __floats2half2_rn(v.x, v.y);
    __half2 h1 = __floats2half2_rn(v.z, v.w);
    __half2* d = (__half2*)(dst + i);
    d[0] = h0; d[1] = h1;
}

// Wc[i][k] = sum_j out_w[i][j] * wv[j][k]   (wv = in_w rows [2E, 3E))
// One block per output row i; 512 threads each own one k; wv reads coalesced.
__global__ void k_fold(const float* __restrict__ out_w,
                       const float* __restrict__ wv,
                       __half* __restrict__ wc) {
    __shared__ float srow[EDIM];
    int i = blockIdx.x;
    int k = threadIdx.x;
    srow[k] = out_w[i * EDIM + k];
    __syncthreads();
    float acc = 0.f;
#pragma unroll 4
    for (int j = 0; j < EDIM; j++) acc = fmaf(srow[j], wv[j * EDIM + k], acc);
    wc[i * EDIM + k] = __float2half(acc);
}

// c[i] = out_b[i] + sum_j out_w[i][j] * bv[j]
__global__ void k_foldc(const float* __restrict__ out_w,
                        const float* __restrict__ out_b,
                        const float* __restrict__ bv,
                        float* __restrict__ c) {
    int i = blockIdx.x * blockDim.x + threadIdx.x;
    if (i >= EDIM) return;
    float acc = out_b[i];
    for (int j = 0; j < EDIM; j++) acc = fmaf(out_w[i * EDIM + j], bv[j], acc);
    c[i] = acc;
}

// ------------------------- fp16 tensor-core GEMM ------------------------------
// out[r][n] = sum_k A[r][k] * W[n][k]  (+bias, +residual, relu), A:[M,K], W:[N,K]
__global__ __launch_bounds__(256) void k_gemm(
    const __half* __restrict__ A, const __half* __restrict__ W,
    const float* __restrict__ bias,
    const float* __restrict__ resf,   // fp32 residual [M, EDIM] or null
    const __half* __restrict__ resh,  // fp16 residual [M, EDIM] or null
    float* __restrict__ outf,         // fp32 out [M, N] or null
    __half* __restrict__ outh,        // fp16 out [M, N] (used if outf null)
    int K, int N, int relu)
{
    __shared__ __half As[BM * LDS];
    __shared__ __half Ws[BN * LDS];

    const int t = threadIdx.x;
    const int brow = blockIdx.y * BM;
    const int bcol = blockIdx.x * BN;
    const int warp = t >> 5, lane = t & 31;
    const int g = lane >> 2, tg = lane & 3;
    const int wm = (warp >> 1) * 32;   // 4 warps along M
    const int wn = (warp & 1) * 32;    // 2 warps along N

    float acc[2][4][4];
#pragma unroll
    for (int a = 0; a < 2; a++)
#pragma unroll
        for (int b = 0; b < 4; b++)
#pragma unroll
            for (int cc = 0; cc < 4; cc++) acc[a][b][cc] = 0.f;

    for (int kt = 0; kt < K; kt += BK) {
        // A tile: 128 x 32 halfs = 512 uint4, 2 per thread
#pragma unroll
        for (int i = 0; i < 2; i++) {
            int idx = t + i * 256;
            int r = idx >> 2, c = (idx & 3) * 8;
            *(uint4*)&As[r * LDS + c] = *(const uint4*)&A[(size_t)(brow + r) * K + kt + c];
        }
        // W tile: 64 x 32 halfs = 256 uint4, 1 per thread
        {
            int r = t >> 2, c = (t & 3) * 8;
            *(uint4*)&Ws[r * LDS + c] = *(const uint4*)&W[(size_t)(bcol + r) * K + kt + c];
        }
        __syncthreads();

#pragma unroll
        for (int kk = 0; kk < BK; kk += 16) {
            uint32_t ra[2][4], rb[4][2];
#pragma unroll
            for (int mi = 0; mi < 2; mi++) {
                int r0 = wm + mi * 16 + g;
                ra[mi][0] = *(const uint32_t*)&As[r0 * LDS + kk + tg * 2];
                ra[mi][1] = *(const uint32_t*)&As[(r0 + 8) * LDS + kk + tg * 2];
                ra[mi][2] = *(const uint32_t*)&As[r0 * LDS + kk + 8 + tg * 2];
                ra[mi][3] = *(const uint32_t*)&As[(r0 + 8) * LDS + kk + 8 + tg * 2];
            }
#pragma unroll
            for (int ni = 0; ni < 4; ni++) {
                int rw = wn + ni * 8 + g;
                rb[ni][0] = *(const uint32_t*)&Ws[rw * LDS + kk + tg * 2];
                rb[ni][1] = *(const uint32_t*)&Ws[rw * LDS + kk + 8 + tg * 2];
            }
#pragma unroll
            for (int mi = 0; mi < 2; mi++)
#pragma unroll
                for (int ni = 0; ni < 4; ni++)
                    asm volatile(
                        "mma.sync.aligned.m16n8k16.row.col.f32.f16.f16.f32 "
                        "{%0,%1,%2,%3}, {%4,%5,%6,%7}, {%8,%9}, {%0,%1,%2,%3};"
                        : "+f"(acc[mi][ni][0]), "+f"(acc[mi][ni][1]),
                          "+f"(acc[mi][ni][2]), "+f"(acc[mi][ni][3])
                        : "r"(ra[mi][0]), "r"(ra[mi][1]), "r"(ra[mi][2]), "r"(ra[mi][3]),
                          "r"(rb[ni][0]), "r"(rb[ni][1]));
        }
        __syncthreads();
    }

    // Epilogue: c0=C[g][tg*2], c1=C[g][tg*2+1], c2=C[g+8][tg*2], c3=C[g+8][tg*2+1]
#pragma unroll
    for (int mi = 0; mi < 2; mi++) {
#pragma unroll
        for (int ni = 0; ni < 4; ni++) {
            int r0 = brow + wm + mi * 16 + g;
            int r1 = r0 + 8;
            int c0 = bcol + wn + ni * 8 + tg * 2;
            float v0 = acc[mi][ni][0], v1 = acc[mi][ni][1];
            float v2 = acc[mi][ni][2], v3 = acc[mi][ni][3];
            float b0 = bias[c0], b1 = bias[c0 + 1];
            v0 += b0; v1 += b1; v2 += b0; v3 += b1;
            if (relu) {
                v0 = fmaxf(v0, 0.f); v1 = fmaxf(v1, 0.f);
                v2 = fmaxf(v2, 0.f); v3 = fmaxf(v3, 0.f);
            }
            if (resf) {  // fp32 residual, ld = EDIM (only used when N == EDIM)
                v0 += resf[(size_t)r0 * EDIM + c0];
                v1 += resf[(size_t)r0 * EDIM + c0 + 1];
                v2 += resf[(size_t)r1 * EDIM + c0];
                v3 += resf[(size_t)r1 * EDIM + c0 + 1];
            }
            if (resh) {  // fp16 residual, ld = EDIM
                v0 += __half2float(resh[(size_t)r0 * EDIM + c0]);
                v1 += __half2float(resh[(size_t)r0 * EDIM + c0 + 1]);
                v2 += __half2float(resh[(size_t)r1 * EDIM + c0]);
                v3 += __half2float(resh[(size_t)r1 * EDIM + c0 + 1]);
            }
            if (outf) {
                outf[(size_t)r0 * N + c0]     = v0;
                outf[(size_t)r0 * N + c0 + 1] = v1;
                outf[(size_t)r1 * N + c0]     = v2;
                outf[(size_t)r1 * N + c0 + 1] = v3;
            } else {
                outh[(size_t)r0 * N + c0]     = __float2half(v0);
                outh[(size_t)r0 * N + c0 + 1] = __float2half(v1);
                outh[(size_t)r1 * N + c0]     = __float2half(v2);
                outh[(size_t)r1 * N + c0 + 1] = __float2half(v3);
            }
        }
    }
}

// ------------------------- row LayerNorm (E=512) ------------------------------
__global__ void k_ln(const float* __restrict__ x,
                     const float* __restrict__ gam, const float* __restrict__ bet,
                     __half* __restrict__ outh,     // fp16 out [M, E] or null
                     float* __restrict__ outf,      // fp32 out (strided) or null
                     int ld_out, int coloff)
{
    int row = blockIdx.x;
    int t = threadIdx.x;  // 128 threads
    const float* xr = x + (size_t)row * EDIM;
    float v[4], s = 0.f, sq = 0.f;
#pragma unroll
    for (int i = 0; i < 4; i++) {
        v[i] = xr[t + i * 128];
        s += v[i];
        sq += v[i] * v[i];
    }
#pragma unroll
    for (int o = 16; o > 0; o >>= 1) {
        s  += __shfl_xor_sync(0xFFFFFFFFu, s, o);
        sq += __shfl_xor_sync(0xFFFFFFFFu, sq, o);
    }
    __shared__ float ss[4], ssq[4];
    int w = t >> 5, l = t & 31;
    if (l == 0) { ss[w] = s; ssq[w] = sq; }
    __syncthreads();
    s  = ss[0] + ss[1] + ss[2] + ss[3];
    sq = ssq[0] + ssq[1] + ssq[2] + ssq[3];
    float mean = s * (1.f / EDIM);
    float var  = sq * (1.f / EDIM) - mean * mean;
    float rstd = rsqrtf(var + 1e-5f);
#pragma unroll
    for (int i = 0; i < 4; i++) {
        int c = t + i * 128;
        float y = (v[i] - mean) * rstd * gam[c] + bet[c];
        if (outh) outh[(size_t)row * EDIM + c] = __float2half(y);
        if (outf) outf[(size_t)row * ld_out + coloff + c] = y;
    }
}

// ------------------------------- launch ---------------------------------------
extern "C" void kernel_launch(void* const* d_in, const int* in_sizes, int n_in,
                              void* d_out, int out_size) {
    const float* dna = (const float*)d_in[0];
    const float* mol = (const float*)d_in[1];
    const float* a_in_w[2]  = { (const float*)d_in[2], (const float*)d_in[6] };
    const float* a_in_b[2]  = { (const float*)d_in[3], (const float*)d_in[7] };
    const float* a_out_w[2] = { (const float*)d_in[4], (const float*)d_in[8] };
    const float* a_out_b[2] = { (const float*)d_in[5], (const float*)d_in[9] };
    const float* lnA_g[2] = { (const float*)d_in[10], (const float*)d_in[12] }; // ln1, ln2
    const float* lnA_b[2] = { (const float*)d_in[11], (const float*)d_in[13] };
    const float* lnB_g[2] = { (const float*)d_in[14], (const float*)d_in[16] }; // ln3, ln4
    const float* lnB_b[2] = { (const float*)d_in[15], (const float*)d_in[17] };
    const float* f_w1[2] = { (const float*)d_in[18], (const float*)d_in[22] };
    const float* f_b1[2] = { (const float*)d_in[19], (const float*)d_in[23] };
    const float* f_w2[2] = { (const float*)d_in[20], (const float*)d_in[24] };
    const float* f_b2[2] = { (const float*)d_in[21], (const float*)d_in[25] };
    float* out = (float*)d_out;

    __half *xh0, *xh1, *hbuf, *ubuf, *wc, *w1h, *w2h;
    float *tbuf, *cbuf;
    cudaGetSymbolAddress((void**)&xh0,  g_xh0);
    cudaGetSymbolAddress((void**)&xh1,  g_xh1);
    cudaGetSymbolAddress((void**)&hbuf, g_h);
    cudaGetSymbolAddress((void**)&ubuf, g_u);
    cudaGetSymbolAddress((void**)&tbuf, g_t);
    cudaGetSymbolAddress((void**)&wc,   g_wc);
    cudaGetSymbolAddress((void**)&cbuf, g_c);
    cudaGetSymbolAddress((void**)&w1h,  g_w1h);
    cudaGetSymbolAddress((void**)&w2h,  g_w2h);

    const int NXE = MROWS * EDIM;   // 16,777,216
    // activations -> fp16
    k_f2h<<<NXE / 1024, 256>>>(dna, xh0, NXE);
    k_f2h<<<NXE / 1024, 256>>>(mol, xh1, NXE);
    // ffn weights -> fp16
    for (int s = 0; s < 2; s++) {
        k_f2h<<<(FFDIM * EDIM) / 1024, 256>>>(f_w1[s], w1h + (size_t)s * FFDIM * EDIM, FFDIM * EDIM);
        k_f2h<<<(EDIM * FFDIM) / 1024, 256>>>(f_w2[s], w2h + (size_t)s * EDIM * FFDIM, EDIM * FFDIM);
    }
    // fold attention: Wc = out_w @ wv, c = out_w @ bv + out_b
    for (int s = 0; s < 2; s++) {
        k_fold<<<EDIM, EDIM>>>(a_out_w[s], a_in_w[s] + 2 * EDIM * EDIM, wc + (size_t)s * EDIM * EDIM);
        k_foldc<<<2, 256>>>(a_out_w[s], a_out_b[s], a_in_b[s] + 2 * EDIM, cbuf + s * EDIM);
    }

    dim3 gE(EDIM / BN, MROWS / BM);   // (8, 256)
    dim3 gF(FFDIM / BN, MROWS / BM);  // (16, 256)

    for (int s = 0; s < 2; s++) {
        const __half* kv   = (s == 0) ? xh1 : xh0;   // stream0 (dna-query) attends mol
        const float*  resq = (s == 0) ? dna : mol;

        // t = res + kv @ Wc^T + c
        k_gemm<<<gE, 256>>>(kv, wc + (size_t)s * EDIM * EDIM, cbuf + s * EDIM,
                            resq, nullptr, tbuf, nullptr, EDIM, EDIM, 0);
        // h = LN(t)
        k_ln<<<MROWS, 128>>>(tbuf, lnA_g[s], lnA_b[s], hbuf, nullptr, 0, 0);
        // u = relu(h @ w1^T + b1)
        k_gemm<<<gF, 256>>>(hbuf, w1h + (size_t)s * FFDIM * EDIM, f_b1[s],
                            nullptr, nullptr, nullptr, ubuf, EDIM, FFDIM, 1);
        // t = h + u @ w2^T + b2
        k_gemm<<<gE, 256>>>(ubuf, w2h + (size_t)s * EDIM * FFDIM, f_b2[s],
                            nullptr, hbuf, tbuf, nullptr, FFDIM, EDIM, 0);
        // out[:, s*512 : s*512+512] = LN(t)
        k_ln<<<MROWS, 128>>>(tbuf, lnB_g[s], lnB_b[s], nullptr, out, 2 * EDIM, s * EDIM);
    }
}

// round 2
// speedup vs baseline: 1.3692x; 1.3692x over previous
#include <cuda_runtime.h>
#include <cuda_fp16.h>
#include <cstdint>

// ----------------------------------------------------------------------------
// CrossAttention_30056181138117 on GB300 (sm_103a) — round 2
//
// Seq-len-1 attention => softmax == 1 => attn out == V projection, folded:
//   att_s = x_other @ Wc_s^T + c_s,  Wc_s = out_w_s @ wv_s
// Per stream: h = LN(x + att); u = relu(h@w1^T+b1); o = LN(h + u@w2^T+b2)
// out = concat(o_dna, o_mol)
//
// Round-2 changes vs round 1:
//  * GEMM: 128x128x32 tiles, 8 warps (32x64 warp tile), 2-stage cp.async
//    double-buffered pipeline (global loads overlap MMA).
//  * All intermediates fp16 (t16 buffer, fp16 residuals from xh), killing the
//    fp32 tbuf round-trips (~600 MB traffic removed).
// ----------------------------------------------------------------------------

#define MROWS 32768
#define EDIM  512
#define FFDIM 1024

#define BM 128
#define BN 128
#define BK 32
#define SPAD 8
#define LDS (BK + SPAD)   // 40 halfs per smem row (80B = 5*16B, cp.async-aligned)

// ------------------------- device scratch (static, no allocs) ---------------
__device__ __half g_xh0[MROWS * EDIM];      // dna fp16 (GEMM input + residual)
__device__ __half g_xh1[MROWS * EDIM];      // mol fp16
__device__ __half g_h  [MROWS * EDIM];      // LN1 output fp16
__device__ __half g_u  [MROWS * FFDIM];     // FFN hidden fp16
__device__ __half g_t16[MROWS * EDIM];      // pre-LN fp16 buffer
__device__ __half g_wc [2 * EDIM * EDIM];   // folded attn weights fp16
__device__ float  g_c  [2 * EDIM];          // folded attn bias fp32
__device__ __half g_w1h[2 * FFDIM * EDIM];  // ffn w1 fp16
__device__ __half g_w2h[2 * EDIM * FFDIM];  // ffn w2 fp16

// ------------------------- helpers -------------------------------------------
__device__ __forceinline__ void cp_async16(void* dst_smem, const void* src_gmem) {
    uint32_t d = (uint32_t)__cvta_generic_to_shared(dst_smem);
    asm volatile("cp.async.cg.shared.global [%0], [%1], 16;\n" :: "r"(d), "l"(src_gmem));
}

// ------------------------- fp32 -> fp16 convert ------------------------------
__global__ void k_f2h(const float* __restrict__ src, __half* __restrict__ dst, int n) {
    int i = (blockIdx.x * blockDim.x + threadIdx.x) * 4;
    if (i >= n) return;
    float4 v = *(const float4*)(src + i);
    __half2* d = (__half2*)(dst + i);
    d[0] = __floats2half2_rn(v.x, v.y);
    d[1] = __floats2half2_rn(v.z, v.w);
}

// Wc[i][k] = sum_j out_w[i][j] * wv[j][k]   (wv = in_w rows [2E, 3E))
__global__ void k_fold(const float* __restrict__ out_w,
                       const float* __restrict__ wv,
                       __half* __restrict__ wc) {
    __shared__ float srow[EDIM];
    int i = blockIdx.x;
    int k = threadIdx.x;
    srow[k] = out_w[i * EDIM + k];
    __syncthreads();
    float acc = 0.f;
#pragma unroll 4
    for (int j = 0; j < EDIM; j++) acc = fmaf(srow[j], wv[j * EDIM + k], acc);
    wc[i * EDIM + k] = __float2half(acc);
}

// c[i] = out_b[i] + sum_j out_w[i][j] * bv[j]
__global__ void k_foldc(const float* __restrict__ out_w,
                        const float* __restrict__ out_b,
                        const float* __restrict__ bv,
                        float* __restrict__ c) {
    int i = blockIdx.x * blockDim.x + threadIdx.x;
    if (i >= EDIM) return;
    float acc = out_b[i];
    for (int j = 0; j < EDIM; j++) acc = fmaf(out_w[i * EDIM + j], bv[j], acc);
    c[i] = acc;
}

// ------------------------- fp16 tensor-core GEMM ------------------------------
// out[r][n] = sum_k A[r][k]*W[n][k] (+bias, optional relu, optional fp16 residual)
// A:[M,K] fp16, W:[N,K] fp16, out fp16. 128x128x32, 2-stage cp.async pipeline.
__global__ __launch_bounds__(256) void k_gemm(
    const __half* __restrict__ A, const __half* __restrict__ W,
    const float* __restrict__ bias,
    const __half* __restrict__ resh,   // fp16 residual [M, EDIM] or null
    __half* __restrict__ outh,         // fp16 out [M, N]
    int K, int N, int relu)
{
    __shared__ __half As[2][BM * LDS];
    __shared__ __half Ws[2][BN * LDS];

    const int t = threadIdx.x;
    const int brow = blockIdx.y * BM;
    const int bcol = blockIdx.x * BN;
    const int warp = t >> 5, lane = t & 31;
    const int g = lane >> 2, tg = lane & 3;
    const int wm = (warp >> 1) * 32;   // 4 warps along M
    const int wn = (warp & 1) * 64;    // 2 warps along N

    // load mapping: 256 threads; each thread moves 2 A rows + 2 W rows (16B each)
    const int lr = t >> 2;          // 0..63
    const int lc = (t & 3) * 8;     // 0,8,16,24 (halfs)

    const __half* Ag = A + (size_t)(brow + lr) * K + lc;
    const __half* Wg = W + (size_t)(bcol + lr) * K + lc;

    float acc[2][8][4];
#pragma unroll
    for (int a = 0; a < 2; a++)
#pragma unroll
        for (int b = 0; b < 8; b++)
#pragma unroll
            for (int c = 0; c < 4; c++) acc[a][b][c] = 0.f;

    const int NT = K / BK;

    // ---- stage-0 prologue ----
    {
        cp_async16(&As[0][lr * LDS + lc],        Ag);
        cp_async16(&As[0][(lr + 64) * LDS + lc], Ag + (size_t)64 * K);
        cp_async16(&Ws[0][lr * LDS + lc],        Wg);
        cp_async16(&Ws[0][(lr + 64) * LDS + lc], Wg + (size_t)64 * K);
        asm volatile("cp.async.commit_group;\n");
    }

    for (int kt = 0; kt < NT; kt++) {
        if (kt + 1 < NT) {
            int s = (kt + 1) & 1;
            int ko = (kt + 1) * BK;
            cp_async16(&As[s][lr * LDS + lc],        Ag + ko);
            cp_async16(&As[s][(lr + 64) * LDS + lc], Ag + ko + (size_t)64 * K);
            cp_async16(&Ws[s][lr * LDS + lc],        Wg + ko);
            cp_async16(&Ws[s][(lr + 64) * LDS + lc], Wg + ko + (size_t)64 * K);
            asm volatile("cp.async.commit_group;\n");
            asm volatile("cp.async.wait_group 1;\n");
        } else {
            asm volatile("cp.async.wait_group 0;\n");
        }
        __syncthreads();

        const int s = kt & 1;
        const __half* as = As[s];
        const __half* ws = Ws[s];

#pragma unroll
        for (int kk = 0; kk < BK; kk += 16) {
            uint32_t ra[2][4], rb[8][2];
#pragma unroll
            for (int mi = 0; mi < 2; mi++) {
                int r0 = wm + mi * 16 + g;
                ra[mi][0] = *(const uint32_t*)&as[r0 * LDS + kk + tg * 2];
                ra[mi][1] = *(const uint32_t*)&as[(r0 + 8) * LDS + kk + tg * 2];
                ra[mi][2] = *(const uint32_t*)&as[r0 * LDS + kk + 8 + tg * 2];
                ra[mi][3] = *(const uint32_t*)&as[(r0 + 8) * LDS + kk + 8 + tg * 2];
            }
#pragma unroll
            for (int ni = 0; ni < 8; ni++) {
                int rw = wn + ni * 8 + g;
                rb[ni][0] = *(const uint32_t*)&ws[rw * LDS + kk + tg * 2];
                rb[ni][1] = *(const uint32_t*)&ws[rw * LDS + kk + 8 + tg * 2];
            }
#pragma unroll
            for (int mi = 0; mi < 2; mi++)
#pragma unroll
                for (int ni = 0; ni < 8; ni++)
                    asm volatile(
                        "mma.sync.aligned.m16n8k16.row.col.f32.f16.f16.f32 "
                        "{%0,%1,%2,%3}, {%4,%5,%6,%7}, {%8,%9}, {%0,%1,%2,%3};"
                        : "+f"(acc[mi][ni][0]), "+f"(acc[mi][ni][1]),
                          "+f"(acc[mi][ni][2]), "+f"(acc[mi][ni][3])
                        : "r"(ra[mi][0]), "r"(ra[mi][1]), "r"(ra[mi][2]), "r"(ra[mi][3]),
                          "r"(rb[ni][0]), "r"(rb[ni][1]));
        }
        __syncthreads();
    }

    // ---- epilogue ----
#pragma unroll
    for (int mi = 0; mi < 2; mi++) {
#pragma unroll
        for (int ni = 0; ni < 8; ni++) {
            int r0 = brow + wm + mi * 16 + g;
            int r1 = r0 + 8;
            int c0 = bcol + wn + ni * 8 + tg * 2;
            float v0 = acc[mi][ni][0], v1 = acc[mi][ni][1];
            float v2 = acc[mi][ni][2], v3 = acc[mi][ni][3];
            float b0 = bias[c0], b1 = bias[c0 + 1];
            v0 += b0; v1 += b1; v2 += b0; v3 += b1;
            if (relu) {
                v0 = fmaxf(v0, 0.f); v1 = fmaxf(v1, 0.f);
                v2 = fmaxf(v2, 0.f); v3 = fmaxf(v3, 0.f);
            }
            if (resh) {   // fp16 residual, ld = EDIM (only when N == EDIM)
                __half2 q0 = *(const __half2*)&resh[(size_t)r0 * EDIM + c0];
                __half2 q1 = *(const __half2*)&resh[(size_t)r1 * EDIM + c0];
                float2 f0 = __half22float2(q0), f1 = __half22float2(q1);
                v0 += f0.x; v1 += f0.y; v2 += f1.x; v3 += f1.y;
            }
            *(__half2*)&outh[(size_t)r0 * N + c0] = __floats2half2_rn(v0, v1);
            *(__half2*)&outh[(size_t)r1 * N + c0] = __floats2half2_rn(v2, v3);
        }
    }
}

// ------------------------- row LayerNorm (E=512, fp16 in) ---------------------
__global__ void k_ln(const __half* __restrict__ x,
                     const float* __restrict__ gam, const float* __restrict__ bet,
                     __half* __restrict__ outh,     // fp16 out [M, E] or null
                     float* __restrict__ outf,      // fp32 out (strided) or null
                     int ld_out, int coloff)
{
    int row = blockIdx.x;
    int t = threadIdx.x;  // 128 threads, each owns 2 half2 = 4 cols
    const __half2* xr = (const __half2*)(x + (size_t)row * EDIM);
    float2 v[2];
    float s = 0.f, sq = 0.f;
#pragma unroll
    for (int i = 0; i < 2; i++) {
        v[i] = __half22float2(xr[t + i * 128]);
        s  += v[i].x + v[i].y;
        sq += v[i].x * v[i].x + v[i].y * v[i].y;
    }
#pragma unroll
    for (int o = 16; o > 0; o >>= 1) {
        s  += __shfl_xor_sync(0xFFFFFFFFu, s, o);
        sq += __shfl_xor_sync(0xFFFFFFFFu, sq, o);
    }
    __shared__ float ss[4], ssq[4];
    int w = t >> 5, l = t & 31;
    if (l == 0) { ss[w] = s; ssq[w] = sq; }
    __syncthreads();
    s  = ss[0] + ss[1] + ss[2] + ss[3];
    sq = ssq[0] + ssq[1] + ssq[2] + ssq[3];
    float mean = s * (1.f / EDIM);
    float var  = sq * (1.f / EDIM) - mean * mean;
    float rstd = rsqrtf(var + 1e-5f);
#pragma unroll
    for (int i = 0; i < 2; i++) {
        int c = 2 * (t + i * 128);
        float y0 = (v[i].x - mean) * rstd * gam[c]     + bet[c];
        float y1 = (v[i].y - mean) * rstd * gam[c + 1] + bet[c + 1];
        if (outh) *(__half2*)&outh[(size_t)row * EDIM + c] = __floats2half2_rn(y0, y1);
        if (outf) {
            outf[(size_t)row * ld_out + coloff + c]     = y0;
            outf[(size_t)row * ld_out + coloff + c + 1] = y1;
        }
    }
}

// ------------------------------- launch ---------------------------------------
extern "C" void kernel_launch(void* const* d_in, const int* in_sizes, int n_in,
                              void* d_out, int out_size) {
    const float* dna = (const float*)d_in[0];
    const float* mol = (const float*)d_in[1];
    const float* a_in_w[2]  = { (const float*)d_in[2], (const float*)d_in[6] };
    const float* a_in_b[2]  = { (const float*)d_in[3], (const float*)d_in[7] };
    const float* a_out_w[2] = { (const float*)d_in[4], (const float*)d_in[8] };
    const float* a_out_b[2] = { (const float*)d_in[5], (const float*)d_in[9] };
    const float* lnA_g[2] = { (const float*)d_in[10], (const float*)d_in[12] }; // ln1, ln2
    const float* lnA_b[2] = { (const float*)d_in[11], (const float*)d_in[13] };
    const float* lnB_g[2] = { (const float*)d_in[14], (const float*)d_in[16] }; // ln3, ln4
    const float* lnB_b[2] = { (const float*)d_in[15], (const float*)d_in[17] };
    const float* f_w1[2] = { (const float*)d_in[18], (const float*)d_in[22] };
    const float* f_b1[2] = { (const float*)d_in[19], (const float*)d_in[23] };
    const float* f_w2[2] = { (const float*)d_in[20], (const float*)d_in[24] };
    const float* f_b2[2] = { (const float*)d_in[21], (const float*)d_in[25] };
    float* out = (float*)d_out;

    __half *xh[2], *hbuf, *ubuf, *t16, *wc, *w1h, *w2h;
    float *cbuf;
    cudaGetSymbolAddress((void**)&xh[0], g_xh0);
    cudaGetSymbolAddress((void**)&xh[1], g_xh1);
    cudaGetSymbolAddress((void**)&hbuf, g_h);
    cudaGetSymbolAddress((void**)&ubuf, g_u);
    cudaGetSymbolAddress((void**)&t16,  g_t16);
    cudaGetSymbolAddress((void**)&wc,   g_wc);
    cudaGetSymbolAddress((void**)&cbuf, g_c);
    cudaGetSymbolAddress((void**)&w1h,  g_w1h);
    cudaGetSymbolAddress((void**)&w2h,  g_w2h);

    const int NXE = MROWS * EDIM;   // 16,777,216
    k_f2h<<<NXE / 1024, 256>>>(dna, xh[0], NXE);
    k_f2h<<<NXE / 1024, 256>>>(mol, xh[1], NXE);
    for (int s = 0; s < 2; s++) {
        k_f2h<<<(FFDIM * EDIM) / 1024, 256>>>(f_w1[s], w1h + (size_t)s * FFDIM * EDIM, FFDIM * EDIM);
        k_f2h<<<(EDIM * FFDIM) / 1024, 256>>>(f_w2[s], w2h + (size_t)s * EDIM * FFDIM, EDIM * FFDIM);
        k_fold<<<EDIM, EDIM>>>(a_out_w[s], a_in_w[s] + 2 * EDIM * EDIM, wc + (size_t)s * EDIM * EDIM);
        k_foldc<<<2, 256>>>(a_out_w[s], a_out_b[s], a_in_b[s] + 2 * EDIM, cbuf + s * EDIM);
    }

    dim3 gE(EDIM / BN, MROWS / BM);   // (4, 256)
    dim3 gF(FFDIM / BN, MROWS / BM);  // (8, 256)

    for (int s = 0; s < 2; s++) {
        const __half* kv = xh[1 - s];   // stream s attends the other stream

        // t = x_s + kv @ Wc^T + c        (residual from fp16 xh[s])
        k_gemm<<<gE, 256>>>(kv, wc + (size_t)s * EDIM * EDIM, cbuf + s * EDIM,
                            xh[s], t16, EDIM, EDIM, 0);
        // h = LN(t)
        k_ln<<<MROWS, 128>>>(t16, lnA_g[s], lnA_b[s], hbuf, nullptr, 0, 0);
        // u = relu(h @ w1^T + b1)
        k_gemm<<<gF, 256>>>(hbuf, w1h + (size_t)s * FFDIM * EDIM, f_b1[s],
                            nullptr, ubuf, EDIM, FFDIM, 1);
        // t = h + u @ w2^T + b2
        k_gemm<<<gE, 256>>>(ubuf, w2h + (size_t)s * EDIM * FFDIM, f_b2[s],
                            hbuf, t16, FFDIM, EDIM, 0);
        // out[:, s*512 : (s+1)*512] = LN(t)
        k_ln<<<MROWS, 128>>>(t16, lnB_g[s], lnB_b[s], nullptr, out, 2 * EDIM, s * EDIM);
    }
}

// round 4
// speedup vs baseline: 1.5466x; 1.1296x over previous
#include <cuda_runtime.h>
#include <cuda_fp16.h>
#include <cstdint>

// ----------------------------------------------------------------------------
// CrossAttention_30056181138117 on GB300 (sm_103a) — round 4
//
// NOTE: harness compiles via compute_103 (family-generic) PTX -> tcgen05 is
// rejected by ptxas. So we maximize the legacy HMMA (mma.sync) path instead.
//
// Seq-len-1 attention => softmax == 1 => attn out == V projection, folded:
//   att_s = x_other @ Wc_s^T + c_s,  Wc_s = out_w_s @ wv_s
// Per stream: h = LN(x + att); u = relu(h@w1^T+b1); o = LN(h + u@w2^T+b2)
//
// Round-4 GEMM: 128x128x32 tiles, 8 warps (32x64 warp tile), 3-stage cp.async
// pipeline with ONE __syncthreads per K-iter, ldmatrix.x4 fragment loads,
// 2 CTAs/SM (launch_bounds(256,2), 60KB dynamic smem).
// ----------------------------------------------------------------------------

#define MROWS 32768
#define EDIM  512
#define FFDIM 1024

#define BM 128
#define BN 128
#define BK 32
#define NSTAGE 3
#define LDS 40                          // halfs per smem row (80B, 16B-aligned)
#define ASTG (BM * LDS)                 // halfs per A stage
#define WSTG (BN * LDS)                 // halfs per W stage
#define GEMM_SMEM (NSTAGE * (ASTG + WSTG) * 2)   // 61440 bytes

// ------------------------- device scratch (static, no allocs) ---------------
__device__ __half g_xh0[MROWS * EDIM];
__device__ __half g_xh1[MROWS * EDIM];
__device__ __half g_h  [MROWS * EDIM];
__device__ __half g_u  [MROWS * FFDIM];
__device__ __half g_t16[MROWS * EDIM];
__device__ __half g_wc [2 * EDIM * EDIM];
__device__ float  g_c  [2 * EDIM];
__device__ __half g_w1h[2 * FFDIM * EDIM];
__device__ __half g_w2h[2 * EDIM * FFDIM];

// ------------------------- helpers -------------------------------------------
__device__ __forceinline__ void cp_async16(uint32_t dst, const void* src) {
    asm volatile("cp.async.cg.shared.global [%0], [%1], 16;\n" :: "r"(dst), "l"(src));
}
__device__ __forceinline__ void ldsm_x4(uint32_t& r0, uint32_t& r1,
                                        uint32_t& r2, uint32_t& r3, uint32_t addr) {
    asm volatile("ldmatrix.sync.aligned.m8n8.x4.shared.b16 {%0,%1,%2,%3}, [%4];"
                 : "=r"(r0), "=r"(r1), "=r"(r2), "=r"(r3) : "r"(addr));
}

// ------------------------- small kernels -------------------------------------
__global__ void k_f2h(const float* __restrict__ src, __half* __restrict__ dst, int n) {
    int i = (blockIdx.x * blockDim.x + threadIdx.x) * 4;
    if (i >= n) return;
    float4 v = *(const float4*)(src + i);
    __half2* d = (__half2*)(dst + i);
    d[0] = __floats2half2_rn(v.x, v.y);
    d[1] = __floats2half2_rn(v.z, v.w);
}

__global__ void k_fold(const float* __restrict__ out_w,
                       const float* __restrict__ wv,
                       __half* __restrict__ wc) {
    __shared__ float srow[EDIM];
    int i = blockIdx.x, k = threadIdx.x;
    srow[k] = out_w[i * EDIM + k];
    __syncthreads();
    float acc = 0.f;
#pragma unroll 4
    for (int j = 0; j < EDIM; j++) acc = fmaf(srow[j], wv[j * EDIM + k], acc);
    wc[i * EDIM + k] = __float2half(acc);
}

__global__ void k_foldc(const float* __restrict__ out_w,
                        const float* __restrict__ out_b,
                        const float* __restrict__ bv,
                        float* __restrict__ c) {
    int i = blockIdx.x * blockDim.x + threadIdx.x;
    if (i >= EDIM) return;
    float acc = out_b[i];
    for (int j = 0; j < EDIM; j++) acc = fmaf(out_w[i * EDIM + j], bv[j], acc);
    c[i] = acc;
}

// ------------------------- fp16 HMMA GEMM -------------------------------------
// out[r][n] = sum_k A[r][k]*W[n][k] (+bias, opt relu, opt fp16 residual) -> fp16
template <int K>
__global__ __launch_bounds__(256, 2) void k_gemm(
    const __half* __restrict__ A, const __half* __restrict__ W,
    const float* __restrict__ bias,
    const __half* __restrict__ resh,   // fp16 residual [M, EDIM] or null
    __half* __restrict__ outh,         // fp16 out [M, N]
    int N, int relu)
{
    constexpr int NT = K / BK;
    extern __shared__ __half smem[];
    __half* Asm = smem;                    // NSTAGE stages of A
    __half* Wsm = smem + NSTAGE * ASTG;    // NSTAGE stages of W

    const uint32_t as_u = (uint32_t)__cvta_generic_to_shared(Asm);
    const uint32_t ws_u = (uint32_t)__cvta_generic_to_shared(Wsm);

    const int t = threadIdx.x;
    const int warp = t >> 5, lane = t & 31;
    const int g = lane >> 2, tg = lane & 3;
    const int brow = blockIdx.y * BM;
    const int bcol = blockIdx.x * BN;
    const int wm = (warp >> 1) * 32;   // 4 warps along M
    const int wn = (warp & 1) * 64;    // 2 warps along N

    // cp.async mapping: 256 threads, each moves 2 A rows + 2 W rows (16B each)
    const int lr = t >> 2;            // 0..63
    const int lc = (t & 3) * 8;       // 0,8,16,24 halfs
    const __half* Ag = A + (size_t)(brow + lr) * K + lc;
    const __half* Wg = W + (size_t)(bcol + lr) * K + lc;

    // ldmatrix lane roles
    const int arow = lane & 15;                              // A tile row in 16-row frag
    const int acol = (lane & 16) >> 1;                       // 0 | 8
    const int browl = (lane & 7) + ((lane & 16) >> 1);       // B row in 16-row group
    const int bcoll = lane & 8;                              // 0 | 8

    float acc[2][8][4];
#pragma unroll
    for (int a = 0; a < 2; a++)
#pragma unroll
        for (int b = 0; b < 8; b++)
#pragma unroll
            for (int c = 0; c < 4; c++) acc[a][b][c] = 0.f;

    auto load_stage = [&](int i, int slot) {
        const int ko = i * BK;
        const uint32_t as = as_u + slot * ASTG * 2;
        const uint32_t ws = ws_u + slot * WSTG * 2;
        cp_async16(as + (lr * LDS + lc) * 2,        Ag + ko);
        cp_async16(as + ((lr + 64) * LDS + lc) * 2, Ag + ko + (size_t)64 * K);
        cp_async16(ws + (lr * LDS + lc) * 2,        Wg + ko);
        cp_async16(ws + ((lr + 64) * LDS + lc) * 2, Wg + ko + (size_t)64 * K);
        asm volatile("cp.async.commit_group;\n");
    };

    // prologue: stages 0..NSTAGE-2
    load_stage(0, 0);
    load_stage(1, 1);

    for (int i = 0; i < NT; i++) {
        if (i + 1 < NT) asm volatile("cp.async.wait_group 1;\n");
        else            asm volatile("cp.async.wait_group 0;\n");
        __syncthreads();

        // prefetch stage i+2 into slot (i+2)%NSTAGE (slot of i-1, already consumed)
        if (i + 2 < NT) load_stage(i + 2, (i + 2) % NSTAGE);

        const int s = i % NSTAGE;
        const uint32_t as = as_u + s * ASTG * 2;
        const uint32_t ws = ws_u + s * WSTG * 2;

#pragma unroll
        for (int kk = 0; kk < BK; kk += 16) {
            uint32_t ra[2][4], rb[8][2];
#pragma unroll
            for (int mi = 0; mi < 2; mi++)
                ldsm_x4(ra[mi][0], ra[mi][1], ra[mi][2], ra[mi][3],
                        as + ((wm + mi * 16 + arow) * LDS + kk + acol) * 2);
#pragma unroll
            for (int np = 0; np < 4; np++)
                ldsm_x4(rb[2 * np][0], rb[2 * np][1], rb[2 * np + 1][0], rb[2 * np + 1][1],
                        ws + ((wn + np * 16 + browl) * LDS + kk + bcoll) * 2);
#pragma unroll
            for (int mi = 0; mi < 2; mi++)
#pragma unroll
                for (int ni = 0; ni < 8; ni++)
                    asm volatile(
                        "mma.sync.aligned.m16n8k16.row.col.f32.f16.f16.f32 "
                        "{%0,%1,%2,%3}, {%4,%5,%6,%7}, {%8,%9}, {%0,%1,%2,%3};"
                        : "+f"(acc[mi][ni][0]), "+f"(acc[mi][ni][1]),
                          "+f"(acc[mi][ni][2]), "+f"(acc[mi][ni][3])
                        : "r"(ra[mi][0]), "r"(ra[mi][1]), "r"(ra[mi][2]), "r"(ra[mi][3]),
                          "r"(rb[ni][0]), "r"(rb[ni][1]));
        }
        __syncthreads();
    }

    // ---- epilogue ----
#pragma unroll
    for (int mi = 0; mi < 2; mi++) {
#pragma unroll
        for (int ni = 0; ni < 8; ni++) {
            int r0 = brow + wm + mi * 16 + g;
            int r1 = r0 + 8;
            int c0 = bcol + wn + ni * 8 + tg * 2;
            float v0 = acc[mi][ni][0], v1 = acc[mi][ni][1];
            float v2 = acc[mi][ni][2], v3 = acc[mi][ni][3];
            float b0 = bias[c0], b1 = bias[c0 + 1];
            v0 += b0; v1 += b1; v2 += b0; v3 += b1;
            if (relu) {
                v0 = fmaxf(v0, 0.f); v1 = fmaxf(v1, 0.f);
                v2 = fmaxf(v2, 0.f); v3 = fmaxf(v3, 0.f);
            }
            if (resh) {
                float2 f0 = __half22float2(*(const __half2*)&resh[(size_t)r0 * EDIM + c0]);
                float2 f1 = __half22float2(*(const __half2*)&resh[(size_t)r1 * EDIM + c0]);
                v0 += f0.x; v1 += f0.y; v2 += f1.x; v3 += f1.y;
            }
            *(__half2*)&outh[(size_t)r0 * N + c0] = __floats2half2_rn(v0, v1);
            *(__half2*)&outh[(size_t)r1 * N + c0] = __floats2half2_rn(v2, v3);
        }
    }
}

// ------------------------- row LayerNorm (E=512, fp16 in) ---------------------
__global__ void k_ln(const __half* __restrict__ x,
                     const float* __restrict__ gam, const float* __restrict__ bet,
                     __half* __restrict__ outh, float* __restrict__ outf,
                     int ld_out, int coloff)
{
    int row = blockIdx.x;
    int t = threadIdx.x;  // 128 threads
    const __half2* xr = (const __half2*)(x + (size_t)row * EDIM);
    float2 v[2];
    float s = 0.f, sq = 0.f;
#pragma unroll
    for (int i = 0; i < 2; i++) {
        v[i] = __half22float2(xr[t + i * 128]);
        s  += v[i].x + v[i].y;
        sq += v[i].x * v[i].x + v[i].y * v[i].y;
    }
#pragma unroll
    for (int o = 16; o > 0; o >>= 1) {
        s  += __shfl_xor_sync(0xFFFFFFFFu, s, o);
        sq += __shfl_xor_sync(0xFFFFFFFFu, sq, o);
    }
    __shared__ float ss[4], ssq[4];
    int w = t >> 5, l = t & 31;
    if (l == 0) { ss[w] = s; ssq[w] = sq; }
    __syncthreads();
    s  = ss[0] + ss[1] + ss[2] + ss[3];
    sq = ssq[0] + ssq[1] + ssq[2] + ssq[3];
    float mean = s * (1.f / EDIM);
    float var  = sq * (1.f / EDIM) - mean * mean;
    float rstd = rsqrtf(var + 1e-5f);
#pragma unroll
    for (int i = 0; i < 2; i++) {
        int c = 2 * (t + i * 128);
        float y0 = (v[i].x - mean) * rstd * gam[c]     + bet[c];
        float y1 = (v[i].y - mean) * rstd * gam[c + 1] + bet[c + 1];
        if (outh) *(__half2*)&outh[(size_t)row * EDIM + c] = __floats2half2_rn(y0, y1);
        if (outf) {
            outf[(size_t)row * ld_out + coloff + c]     = y0;
            outf[(size_t)row * ld_out + coloff + c + 1] = y1;
        }
    }
}

// ------------------------------- launch ---------------------------------------
extern "C" void kernel_launch(void* const* d_in, const int* in_sizes, int n_in,
                              void* d_out, int out_size) {
    const float* a_in_w[2]  = { (const float*)d_in[2], (const float*)d_in[6] };
    const float* a_in_b[2]  = { (const float*)d_in[3], (const float*)d_in[7] };
    const float* a_out_w[2] = { (const float*)d_in[4], (const float*)d_in[8] };
    const float* a_out_b[2] = { (const float*)d_in[5], (const float*)d_in[9] };
    const float* lnA_g[2] = { (const float*)d_in[10], (const float*)d_in[12] };
    const float* lnA_b[2] = { (const float*)d_in[11], (const float*)d_in[13] };
    const float* lnB_g[2] = { (const float*)d_in[14], (const float*)d_in[16] };
    const float* lnB_b[2] = { (const float*)d_in[15], (const float*)d_in[17] };
    const float* f_w1[2] = { (const float*)d_in[18], (const float*)d_in[22] };
    const float* f_b1[2] = { (const float*)d_in[19], (const float*)d_in[23] };
    const float* f_w2[2] = { (const float*)d_in[20], (const float*)d_in[24] };
    const float* f_b2[2] = { (const float*)d_in[21], (const float*)d_in[25] };
    float* out = (float*)d_out;

    __half *xh[2], *hbuf, *ubuf, *t16, *wc, *w1h, *w2h;
    float *cbuf;
    cudaGetSymbolAddress((void**)&xh[0], g_xh0);
    cudaGetSymbolAddress((void**)&xh[1], g_xh1);
    cudaGetSymbolAddress((void**)&hbuf, g_h);
    cudaGetSymbolAddress((void**)&ubuf, g_u);
    cudaGetSymbolAddress((void**)&t16,  g_t16);
    cudaGetSymbolAddress((void**)&wc,   g_wc);
    cudaGetSymbolAddress((void**)&cbuf, g_c);
    cudaGetSymbolAddress((void**)&w1h,  g_w1h);
    cudaGetSymbolAddress((void**)&w2h,  g_w2h);

    cudaFuncSetAttribute(k_gemm<EDIM>,
                         cudaFuncAttributeMaxDynamicSharedMemorySize, GEMM_SMEM);
    cudaFuncSetAttribute(k_gemm<FFDIM>,
                         cudaFuncAttributeMaxDynamicSharedMemorySize, GEMM_SMEM);

    const int NXE = MROWS * EDIM;
    k_f2h<<<NXE / 1024, 256>>>((const float*)d_in[0], xh[0], NXE);
    k_f2h<<<NXE / 1024, 256>>>((const float*)d_in[1], xh[1], NXE);
    for (int s = 0; s < 2; s++) {
        k_f2h<<<(FFDIM * EDIM) / 1024, 256>>>(f_w1[s], w1h + (size_t)s * FFDIM * EDIM, FFDIM * EDIM);
        k_f2h<<<(EDIM * FFDIM) / 1024, 256>>>(f_w2[s], w2h + (size_t)s * EDIM * FFDIM, EDIM * FFDIM);
        k_fold<<<EDIM, EDIM>>>(a_out_w[s], a_in_w[s] + 2 * EDIM * EDIM, wc + (size_t)s * EDIM * EDIM);
        k_foldc<<<2, 256>>>(a_out_w[s], a_out_b[s], a_in_b[s] + 2 * EDIM, cbuf + s * EDIM);
    }

    dim3 gE(EDIM / BN, MROWS / BM);    // (4, 256)
    dim3 gF(FFDIM / BN, MROWS / BM);   // (8, 256)

    for (int s = 0; s < 2; s++) {
        const __half* kv = xh[1 - s];

        // t = x_s + kv @ Wc^T + c
        k_gemm<EDIM><<<gE, 256, GEMM_SMEM>>>(kv, wc + (size_t)s * EDIM * EDIM,
                                             cbuf + s * EDIM, xh[s], t16, EDIM, 0);
        // h = LN(t)
        k_ln<<<MROWS, 128>>>(t16, lnA_g[s], lnA_b[s], hbuf, nullptr, 0, 0);
        // u = relu(h @ w1^T + b1)
        k_gemm<EDIM><<<gF, 256, GEMM_SMEM>>>(hbuf, w1h + (size_t)s * FFDIM * EDIM,
                                             f_b1[s], nullptr, ubuf, FFDIM, 1);
        // t = h + u @ w2^T + b2
        k_gemm<FFDIM><<<gE, 256, GEMM_SMEM>>>(ubuf, w2h + (size_t)s * EDIM * FFDIM,
                                              f_b2[s], hbuf, t16, EDIM, 0);
        // out[:, s*512 : (s+1)*512] = LN(t)
        k_ln<<<MROWS, 128>>>(t16, lnB_g[s], lnB_b[s], nullptr, out, 2 * EDIM, s * EDIM);
    }
}